// round 14
// baseline (speedup 1.0000x reference)
#include <cuda_runtime.h>
#include <cuda_fp16.h>
#include <cstdint>

// ============================================================================
// GaussianMLP fused — sm_103 plain target, fp16 mma.sync.m16n8k16.
// R14: 512 thr, 4x4 warps, M32xN64; THREE K=128 mega-stages (1 L1 + 2 L2),
//      2-slot 68KB ring, x staged once (272B rows overlaid in h region),
//      4 total barriers, interleaved W2 -> register-only epilogue.
// ============================================================================

#define NTILES 4096

__device__ __forceinline__ uint32_t smem_u32(const void* p) {
    uint32_t a;
    asm("{ .reg .u64 t; cvta.to.shared.u64 t, %1; cvt.u32.u64 %0, t; }" : "=r"(a) : "l"(p));
    return a;
}
__device__ __forceinline__ void mma16(float* c, const uint32_t* a, uint32_t b0, uint32_t b1) {
    asm volatile(
        "mma.sync.aligned.m16n8k16.row.col.f32.f16.f16.f32 "
        "{%0,%1,%2,%3},{%4,%5,%6,%7},{%8,%9},{%0,%1,%2,%3};"
        : "+f"(c[0]), "+f"(c[1]), "+f"(c[2]), "+f"(c[3])
        : "r"(a[0]), "r"(a[1]), "r"(a[2]), "r"(a[3]), "r"(b0), "r"(b1));
}
__device__ __forceinline__ void ldsm4(uint32_t* r, uint32_t addr) {
    asm volatile("ldmatrix.sync.aligned.m8n8.x4.shared.b16 {%0,%1,%2,%3}, [%4];"
                 : "=r"(r[0]), "=r"(r[1]), "=r"(r[2]), "=r"(r[3]) : "r"(addr));
}
#define CP16CG(dst, src) \
    asm volatile("cp.async.cg.shared.global [%0], [%1], 16;" :: "r"(dst), "l"(src))
#define CP_COMMIT() asm volatile("cp.async.commit_group;" ::: "memory")
#define CP_WAIT1()  asm volatile("cp.async.wait_group 1;" ::: "memory")
#define CP_WAIT0()  asm volatile("cp.async.wait_group 0;" ::: "memory")

// ---------------- pre-converted half weights, [n][k] -------------------------
__device__ __align__(16) __half g_wemb_h[256 * 128];
// W2 interleaved at 8-col blocks: n' block 2t -> W_mean cols [8t,8t+8),
//                                 n' block 2t+1 -> W_logvar cols [8t,8t+8)
__device__ __align__(16) __half g_w2_h[256 * 256];

__global__ void prep_kernel(const float* __restrict__ We,
                            const float* __restrict__ Wm,
                            const float* __restrict__ Wl) {
    int i = blockIdx.x * 256 + threadIdx.x;
    if (i < 32768) {
        int n = i >> 7, k = i & 127;
        g_wemb_h[i] = __float2half(We[k * 256 + n]);
    } else if (i < 98304) {
        int j = i - 32768;
        int np = j >> 8, k = j & 255;
        int c = ((np >> 4) << 3) | (np & 7);
        float v = ((np >> 3) & 1) ? Wl[k * 128 + c] : Wm[k * 128 + c];
        g_w2_h[j] = __float2half(v);
    }
}

// ---------------- SMEM map (208896 B) ----------------------------------------
// hs/x : x half tile [128][272B] (L1), then h [128][528B] (L2)   67584
// ring : 2 slots x [256 rows][272B] (256B data + 16 pad)        139264
// bias : 2048
#define HS_OFF    0u
#define S0_OFF    67584u
#define S1_OFF    137216u
#define SBE_OFF   206848u
#define SBM_OFF   207872u
#define SBL_OFF   208384u
#define SMEM_TOTAL 208896
#define HS_SB 528u        // h row stride (bytes)
#define XR_SB 272u        // x row stride (bytes)
#define WR_SB 272u        // ring row stride (bytes)

__global__ void __launch_bounds__(512, 1)
gauss_kernel(const float* __restrict__ x, const float* __restrict__ eps,
             const float* __restrict__ be, const float* __restrict__ bm,
             const float* __restrict__ bl, float* __restrict__ out) {
    extern __shared__ char smem[];
    const uint32_t sm = smem_u32(smem);
    float* sbe = (float*)(smem + SBE_OFF);
    float* sbm = (float*)(smem + SBM_OFF);
    float* sbl = (float*)(smem + SBL_OFF);

    const int tid  = threadIdx.x;
    const int wid  = tid >> 5, lane = tid & 31;
    const int g    = lane >> 2, tg = lane & 3;
    const int mw   = wid & 3;                 // M block (32 rows)
    const int nw   = wid >> 2;                // N block (64 n'-cols)
    const int nb   = nw * 64;
    const size_t tile = blockIdx.x;

    const int fr_row = lane & 15;
    const uint32_t fr_kb = (lane & 16) ? 16u : 0u;

    if (tid < 256) sbe[tid] = be[tid];
    if (tid < 128) { sbm[tid] = bm[tid]; sbl[tid] = bl[tid]; }

    const float* xg = x + tile * 16384;

    // ---- weight mega-stage issuer: [256 rows][128 k-halves] -> slot ---------
    // i=0: W1 -> slot0 ; i=1: W2 k[0:128) -> slot1 ; i=2: W2 k[128:256) -> slot0
    auto issue_w = [&](int i) {
        const uint32_t base = sm + ((i == 1) ? S1_OFF : S0_OFF);
        const __half* w = (i == 0) ? g_wemb_h : (g_w2_h + (i - 1) * 128);
        const int rs = (i == 0) ? 128 : 256;
        const int row = tid >> 1, h = tid & 1;       // 256 rows x 2 thr
        const __half* src = w + row * rs + h * 64;
        uint32_t dst = base + (uint32_t)row * WR_SB + (uint32_t)(h * 128);
        CP16CG(dst,       src);
        CP16CG(dst + 16u, src + 8);
        CP16CG(dst + 32u, src + 16);
        CP16CG(dst + 48u, src + 24);
        CP16CG(dst + 64u, src + 32);
        CP16CG(dst + 80u, src + 40);
        CP16CG(dst + 96u, src + 48);
        CP16CG(dst + 112u, src + 56);
        CP_COMMIT();
    };

    float acc[2][8][4];
    #pragma unroll
    for (int m = 0; m < 2; m++)
        #pragma unroll
        for (int n = 0; n < 8; n++)
            #pragma unroll
            for (int c = 0; c < 4; c++) acc[m][n][c] = 0.0f;

    // ---- prologue: W1, W2a in flight; stage entire x tile (fp32->half) ------
    issue_w(0);
    issue_w(1);
    {
        const int x_row = tid >> 2, x_q = tid & 3;   // 128 rows x 4 thr
        const float4* p = (const float4*)(xg + x_row * 128 + x_q * 32);
        float4 v[8];
        #pragma unroll
        for (int j = 0; j < 8; j++) v[j] = p[j];
        uint32_t base = HS_OFF + (uint32_t)x_row * XR_SB + (uint32_t)(x_q * 64);
        #pragma unroll
        for (int j = 0; j < 4; j++) {
            __half2 h0 = __floats2half2_rn(v[2 * j].x, v[2 * j].y);
            __half2 h1 = __floats2half2_rn(v[2 * j].z, v[2 * j].w);
            __half2 h2 = __floats2half2_rn(v[2 * j + 1].x, v[2 * j + 1].y);
            __half2 h3 = __floats2half2_rn(v[2 * j + 1].z, v[2 * j + 1].w);
            uint4 u;
            u.x = *(uint32_t*)&h0; u.y = *(uint32_t*)&h1;
            u.z = *(uint32_t*)&h2; u.w = *(uint32_t*)&h3;
            *(uint4*)(smem + base + (uint32_t)(j * 16)) = u;
        }
    }
    CP_WAIT1();                      // W1 complete (W2a may be pending)
    __syncthreads();                 // barrier 1: W1 + x visible

    // ======================= layer 1 (one K=128 block) =======================
    {
        const uint32_t a_base = sm + HS_OFF
            + (uint32_t)(mw * 32 + fr_row) * XR_SB + fr_kb;
        const uint32_t b_base = sm + S0_OFF
            + (uint32_t)(nb + fr_row) * WR_SB + fr_kb;
        #pragma unroll
        for (int kk = 0; kk < 8; kk++) {
            uint32_t A0[4], A1[4];
            ldsm4(A0, a_base + (uint32_t)(kk * 32));
            ldsm4(A1, a_base + 16u * XR_SB + (uint32_t)(kk * 32));
            #pragma unroll
            for (int q = 0; q < 4; q++) {
                uint32_t B[4];
                ldsm4(B, b_base + (uint32_t)(q * 16) * WR_SB + (uint32_t)(kk * 32));
                mma16(acc[0][2 * q],     A0, B[0], B[2]);
                mma16(acc[0][2 * q + 1], A0, B[1], B[3]);
                mma16(acc[1][2 * q],     A1, B[0], B[2]);
                mma16(acc[1][2 * q + 1], A1, B[1], B[3]);
            }
        }
    }
    __syncthreads();                 // barrier 2: x + slot0 reads done

    // ---- h = half(relu(acc + b_emb)) -> hs ; issue W2b -> slot0 -------------
    issue_w(2);
    {
        #pragma unroll
        for (int m = 0; m < 2; m++) {
            const int r0 = mw * 32 + m * 16 + g;
            #pragma unroll
            for (int n = 0; n < 8; n++) {
                int col = nb + n * 8 + 2 * tg;
                float b0v = sbe[col], b1v = sbe[col + 1];
                __half2 v0 = __floats2half2_rn(fmaxf(acc[m][n][0] + b0v, 0.0f),
                                               fmaxf(acc[m][n][1] + b1v, 0.0f));
                __half2 v1 = __floats2half2_rn(fmaxf(acc[m][n][2] + b0v, 0.0f),
                                               fmaxf(acc[m][n][3] + b1v, 0.0f));
                *(__half2*)(smem + HS_OFF + (uint32_t)r0 * HS_SB + (uint32_t)(col * 2))       = v0;
                *(__half2*)(smem + HS_OFF + (uint32_t)(r0 + 8) * HS_SB + (uint32_t)(col * 2)) = v1;
            }
        }
    }
    #pragma unroll
    for (int m = 0; m < 2; m++)
        #pragma unroll
        for (int n = 0; n < 8; n++)
            #pragma unroll
            for (int c = 0; c < 4; c++) acc[m][n][c] = 0.0f;
    CP_WAIT1();                      // W2a complete (W2b pending)
    __syncthreads();                 // barrier 3: h + W2a visible

    // ======================= layer 2a (K=128 from slot1) =====================
    {
        const uint32_t a_base = sm + HS_OFF
            + (uint32_t)(mw * 32 + fr_row) * HS_SB + fr_kb;
        const uint32_t b_base = sm + S1_OFF
            + (uint32_t)(nb + fr_row) * WR_SB + fr_kb;
        #pragma unroll
        for (int kk = 0; kk < 8; kk++) {
            uint32_t A0[4], A1[4];
            ldsm4(A0, a_base + (uint32_t)(kk * 32));
            ldsm4(A1, a_base + 16u * HS_SB + (uint32_t)(kk * 32));
            #pragma unroll
            for (int q = 0; q < 4; q++) {
                uint32_t B[4];
                ldsm4(B, b_base + (uint32_t)(q * 16) * WR_SB + (uint32_t)(kk * 32));
                mma16(acc[0][2 * q],     A0, B[0], B[2]);
                mma16(acc[0][2 * q + 1], A0, B[1], B[3]);
                mma16(acc[1][2 * q],     A1, B[0], B[2]);
                mma16(acc[1][2 * q + 1], A1, B[1], B[3]);
            }
        }
    }
    CP_WAIT0();                      // W2b complete
    __syncthreads();                 // barrier 4: W2b visible

    // ======================= layer 2b (K=128 from slot0) =====================
    {
        const uint32_t a_base = sm + HS_OFF
            + (uint32_t)(mw * 32 + fr_row) * HS_SB + 256u + fr_kb;
        const uint32_t b_base = sm + S0_OFF
            + (uint32_t)(nb + fr_row) * WR_SB + fr_kb;
        #pragma unroll
        for (int kk = 0; kk < 8; kk++) {
            uint32_t A0[4], A1[4];
            ldsm4(A0, a_base + (uint32_t)(kk * 32));
            ldsm4(A1, a_base + 16u * HS_SB + (uint32_t)(kk * 32));
            #pragma unroll
            for (int q = 0; q < 4; q++) {
                uint32_t B[4];
                ldsm4(B, b_base + (uint32_t)(q * 16) * WR_SB + (uint32_t)(kk * 32));
                mma16(acc[0][2 * q],     A0, B[0], B[2]);
                mma16(acc[0][2 * q + 1], A0, B[1], B[3]);
                mma16(acc[1][2 * q],     A1, B[0], B[2]);
                mma16(acc[1][2 * q + 1], A1, B[1], B[3]);
            }
        }
    }

    // ====== epilogue: register-only (interleaved W2 pairs mean/logvar) =======
    {
        const float* eg = eps + tile * 16384;
        float* oz = out + tile * 16384;
        float* om = out + 67108864ull + tile * 16384;
        float* ol = out + 134217728ull + tile * 16384;
        #pragma unroll
        for (int m = 0; m < 2; m++) {
            const int rA = mw * 32 + m * 16 + g, rB = rA + 8;
            float2 eA[4], eB[4];
            #pragma unroll
            for (int e = 0; e < 4; e++) {
                const int c = 8 * (4 * nw + e) + 2 * tg;
                eA[e] = *(const float2*)&eg[rA * 128 + c];
                eB[e] = *(const float2*)&eg[rB * 128 + c];
            }
            #pragma unroll
            for (int e = 0; e < 4; e++) {
                const int c = 8 * (4 * nw + e) + 2 * tg;
                float bm0 = sbm[c], bm1 = sbm[c + 1];
                float bl0 = sbl[c], bl1 = sbl[c + 1];
                float me0 = acc[m][2 * e][0] + bm0, me1 = acc[m][2 * e][1] + bm1;
                float me2 = acc[m][2 * e][2] + bm0, me3 = acc[m][2 * e][3] + bm1;
                float lv0 = acc[m][2 * e + 1][0] + bl0, lv1 = acc[m][2 * e + 1][1] + bl1;
                float lv2 = acc[m][2 * e + 1][2] + bl0, lv3 = acc[m][2 * e + 1][3] + bl1;
                float2 z0, z1;
                z0.x = fmaf(__expf(0.5f * lv0), eA[e].x, me0);
                z0.y = fmaf(__expf(0.5f * lv1), eA[e].y, me1);
                z1.x = fmaf(__expf(0.5f * lv2), eB[e].x, me2);
                z1.y = fmaf(__expf(0.5f * lv3), eB[e].y, me3);
                *(float2*)&oz[rA * 128 + c] = z0;
                *(float2*)&oz[rB * 128 + c] = z1;
                *(float2*)&om[rA * 128 + c] = make_float2(me0, me1);
                *(float2*)&om[rB * 128 + c] = make_float2(me2, me3);
                *(float2*)&ol[rA * 128 + c] = make_float2(lv0, lv1);
                *(float2*)&ol[rB * 128 + c] = make_float2(lv2, lv3);
            }
        }
    }
}

// ---------------------------------------------------------------------------

extern "C" void kernel_launch(void* const* d_in, const int* in_sizes, int n_in,
                              void* d_out, int out_size) {
    const float* x   = (const float*)d_in[0];
    const float* eps = (const float*)d_in[1];
    const float* We  = (const float*)d_in[2];
    const float* be  = (const float*)d_in[3];
    const float* Wm  = (const float*)d_in[4];
    const float* bm  = (const float*)d_in[5];
    const float* Wl  = (const float*)d_in[6];
    const float* bl  = (const float*)d_in[7];
    float* out = (float*)d_out;

    cudaFuncSetAttribute(gauss_kernel, cudaFuncAttributeMaxDynamicSharedMemorySize, SMEM_TOTAL);
    prep_kernel<<<384, 256>>>(We, Wm, Wl);
    gauss_kernel<<<NTILES, 512, SMEM_TOTAL>>>(x, eps, be, bm, bl, out);
}